// round 13
// baseline (speedup 1.0000x reference)
#include <cuda_runtime.h>
#include <math.h>

#define T_LEN    8192
#define NDELAY   360
#define NTHREADS 1024
#define FULLMASK 0xffffffffu

// smem float layout: X | B | Y, each with front pad (zeroed) + 1024 tail pad
#define FPX 424                   // >= L1+1 max (421)
#define FPB 520                   // >= 2*L1+2 max when K=2 path used (514)
#define FPY 8                     // >= NT-1 max (4)
#define OX  0
#define OB  (OX + FPX + T_LEN + 1024)
#define OY  (OB + FPB + T_LEN + 1024)
#define SMEM_FLOATS (OY + FPY + T_LEN + 1024)

// ---------------------------------------------------------------------------
// y_t = x_t - a1*y_{t-L1} - a2*y_{t-L2}; exactly two taps (straight-through
// one-hot exactly hard in fp32). L2 = L1+1 unless m==359 (fallback kept).
// 1/(1+s) = (1-s)/(1-s^2) = (1-s)(1+s^2)/(1-s^4).
// K=2 when L1<=256 (W=4*L1<=1024), else K=1 (W=2*L1<=840). Serial remainder
// y = w + s^{2^K} y has taps at CONSECUTIVE lags W..W+NT-1 (since L2=L1+1):
// thread p <-> slot p; tap0 = own prev-round register; tap k = shfl_up(k),
// boundary lanes (lane<k) read Y from an earlier round (front-pad safe).
// 8-16 serial rounds total, ~120cyc each; everything else is 2-3 parallel
// register-carried FIR passes.
// ---------------------------------------------------------------------------

__device__ __forceinline__ float tanh_fast(float x) {
    x = fminf(fmaxf(x, -15.0f), 15.0f);
    float e = __expf(2.0f * x);
    return (e - 1.0f) * __frcp_rn(e + 1.0f);
}

template <int NT>
__device__ __forceinline__ void serial_run(const float* __restrict__ Cw,
                                           float* __restrict__ Y,
                                           const float* c, int W) {
    const int p    = threadIdx.x;
    const int lane = p & 31;

    // round 0: y = w on [0, W); strays (p >= W) write tail/next-region slots
    // that later rounds overwrite before any valid thread reads them.
    float yp = Cw[p];
    Y[p] = yp;
    __syncthreads();

    int s0 = W;
    while (s0 < T_LEN) {
        float cx = Cw[s0 + p];
        float u[NT - 1];
#pragma unroll
        for (int k = 1; k < NT; k++) {
            u[k - 1] = __shfl_up_sync(FULLMASK, yp, k);
            if (lane < k) u[k - 1] = Y[s0 - W + p - k];   // predicated LDS
        }
        float acc = fmaf(c[0], yp, cx);
#pragma unroll
        for (int k = 1; k < NT; k++) acc = fmaf(c[k], u[k - 1], acc);
        Y[s0 + p] = acc;
        __syncthreads();
        yp = acc;
        s0 += W;
    }
}

__global__ void __launch_bounds__(NTHREADS, 1)
ks_fused_kernel(const float* __restrict__ x,
                const float* __restrict__ gumbel,
                const float* __restrict__ delayp,
                const float* __restrict__ fb,
                const float* __restrict__ rc,
                float* __restrict__ out) {
    extern __shared__ float sm[];
    float* Xd = sm + OX + FPX;
    float* Bd = sm + OB + FPB;
    float* Yd = sm + OY + FPY;

    __shared__ float s_rv[32];
    __shared__ int   s_ri[32];
    __shared__ int   s_m;

    const int tid  = threadIdx.x;
    const int row  = blockIdx.x;
    const int lane = tid & 31;
    const int wid  = tid >> 5;
    const float* xr = x + (size_t)row * T_LEN;
    float*       yr = out + (size_t)row * T_LEN;

    // --- stage x (coalesced float4; LDG latency hidden under setup) ---
    {
        const float4* x4 = (const float4*)xr;
        float4* s4 = (float4*)Xd;
        s4[tid]            = x4[tid];
        s4[tid + NTHREADS] = x4[tid + NTHREADS];
    }

    // --- zero the (small) front pads ---
    if (tid < FPX) sm[OX + tid] = 0.0f;
    if (tid < FPB) sm[OB + tid] = 0.0f;
    if (tid < FPY) sm[OY + tid] = 0.0f;

    // --- argmax over 360 logits (first-index tie-break) ---
    float lv = -INFINITY;
    int   li = tid;
    if (tid < NDELAY) lv = delayp[tid] + gumbel[tid];
#pragma unroll
    for (int off = 16; off > 0; off >>= 1) {
        float ov = __shfl_down_sync(FULLMASK, lv, off);
        int   oi = __shfl_down_sync(FULLMASK, li, off);
        if (ov > lv || (ov == lv && oi < li)) { lv = ov; li = oi; }
    }
    if (lane == 0) { s_rv[wid] = lv; s_ri[wid] = li; }

    // --- scalar coefficients (redundant per thread, deterministic) ---
    float k1 = tanh_fast(tanh_fast(rc[0]));
    float k2 = tanh_fast(tanh_fast(rc[1]));
    float a1 = k1 * (1.0f - k2);
    float a2 = fminf(fmaxf(k2, -0.999f), 0.999f);
    float bound = 0.999f - fabsf(a2);
    a1 = fminf(fmaxf(a1, -bound), bound);
    float sg = __frcp_rn(1.0f + __expf(-fb[0]));
    float g  = __powf(sg, 0.45f);
    a1 *= g;
    a2 *= g;

    __syncthreads();
    if (tid < 32) {
        lv = s_rv[lane];
        li = s_ri[lane];
#pragma unroll
        for (int off = 16; off > 0; off >>= 1) {
            float ov = __shfl_down_sync(FULLMASK, lv, off);
            int   oi = __shfl_down_sync(FULLMASK, li, off);
            if (ov > lv || (ov == lv && oi < li)) { lv = ov; li = oi; }
        }
        if (lane == 0) s_m = li;
    }
    __syncthreads();   // staging + pads + argmax complete

    const int m  = s_m;
    const int L1 = 61 + m;
    const int L2 = 61 + ((m + 1) % NDELAY);

    if (L2 != L1 + 1) {
        // --- fallback (m == 359 only): in-place barrier rounds, width C ---
        const int C = (L1 < L2) ? L1 : L2;
        for (int s0 = C; s0 < T_LEN; s0 += C) {
            __syncthreads();
            const int t = s0 + tid;
            if (tid < C && t < T_LEN)
                Xd[t] = Xd[t] - a1 * Xd[t - L1] - a2 * Xd[t - L2];
        }
        __syncthreads();
        float4* o4 = (float4*)yr;
        const float4* r4 = (const float4*)Xd;
        o4[tid]            = r4[tid];
        o4[tid + NTHREADS] = r4[tid + NTHREADS];
        return;
    }

    const float a1_2 = a1 * a1, a2_2 = a2 * a2;

    // --- pass 1: B = (1 - s) X, register carry (lags L1, L1+1) ---
    float rc8[8];
#pragma unroll
    for (int i = 0; i < 8; i++) {
        const int t = i * NTHREADS + tid;
        float w = fmaf(-a1, Xd[t - L1], Xd[t]);
        w = fmaf(-a2, Xd[t - L1 - 1], w);
        Bd[t] = w;
        rc8[i] = w;
    }
    __syncthreads();

    if (L1 <= 256) {
        // --- K=2: pass 2: C = (1 + s^2) B -> reuse X region ---
        const float q0 = a1_2, q1 = 2.0f * a1 * a2, q2 = a2_2;
        const int gl = 2 * L1;
#pragma unroll
        for (int i = 0; i < 8; i++) {
            const int t = i * NTHREADS + tid;
            float w = fmaf(q0, Bd[t - gl], rc8[i]);
            w = fmaf(q1, Bd[t - gl - 1], w);
            w = fmaf(q2, Bd[t - gl - 2], w);
            Xd[t] = w;
        }
        __syncthreads();
        // serial: y = w + s^4 y, taps at 4L1..4L1+4
        const float c[5] = { a1_2 * a1_2, 4.0f * a1_2 * a1 * a2,
                             6.0f * a1_2 * a2_2, 4.0f * a1 * a2_2 * a2,
                             a2_2 * a2_2 };
        serial_run<5>(Xd, Yd, c, 4 * L1);
    } else {
        // --- K=1: serial: y = w + s^2 y, taps at 2L1..2L1+2 ---
        const float c[3] = { a1_2, 2.0f * a1 * a2, a2_2 };
        serial_run<3>(Bd, Yd, c, 2 * L1);
    }

    // --- vectorized writeback ---
    {
        float4* o4 = (float4*)yr;
        const float4* r4 = (const float4*)Yd;
        o4[tid]            = r4[tid];
        o4[tid + NTHREADS] = r4[tid + NTHREADS];
    }
}

// ---------------------------------------------------------------------------
// inputs: excitation[128*8192] f32, gumbel[360], delay_param[360],
//         feedback_gain[1], reflection_coeffs[2]; output f32 [128*8192]
// ---------------------------------------------------------------------------
extern "C" void kernel_launch(void* const* d_in, const int* in_sizes, int n_in,
                              void* d_out, int out_size) {
    const float* x      = (const float*)d_in[0];
    const float* gumbel = (const float*)d_in[1];
    const float* delayp = (const float*)d_in[2];
    const float* fb     = (const float*)d_in[3];
    const float* rc     = (const float*)d_in[4];
    float* out = (float*)d_out;

    const int rows = in_sizes[0] / T_LEN;
    const int smem_bytes = SMEM_FLOATS * sizeof(float);

    cudaFuncSetAttribute(ks_fused_kernel,
                         cudaFuncAttributeMaxDynamicSharedMemorySize, smem_bytes);
    ks_fused_kernel<<<rows, NTHREADS, smem_bytes>>>(x, gumbel, delayp, fb, rc, out);
}